// round 14
// baseline (speedup 1.0000x reference)
#include <cuda_runtime.h>
#include <cuda_fp16.h>
#include <math.h>
#include <stdint.h>

#define D_MODEL 768
#define D_INNER 1536
#define D_STATE 16
#define DT_RANK 96
#define SEQ     2048
#define BATCH   2
#define MTOT    (BATCH * SEQ)   // 4096
#define XDBL_W  128             // DT_RANK + 2*D_STATE

// ---------------- scratch (device globals: allocation-free) ----------------
__device__ float g_xdbl [MTOT * XDBL_W];
__device__ float g_delta[MTOT * D_INNER];

__device__ __align__(16) __half g_xnh[MTOT * D_MODEL];   // LN out (GEMM1 A)
__device__ __align__(16) __half g_uh [MTOT * D_INNER];   // pre-conv u (half)
__device__ __align__(16) __half g_vh [MTOT * D_INNER];   // gate v (half)
__device__ __align__(16) __half g_uch[MTOT * D_INNER];   // conv+silu out (GEMM2 A, scan u)
__device__ __align__(16) __half g_xdh[MTOT * XDBL_W];    // xdbl half (GEMM3 A)
__device__ __align__(16) __half g_yh [MTOT * D_INNER];   // scan out (GEMM_out A)

// transposed half weights Wt[n][k] = W[k][n]
__device__ __align__(16) __half g_wint [2 * D_INNER * D_MODEL];  // [3072][768]
__device__ __align__(16) __half g_wxpt [XDBL_W * D_INNER];       // [128][1536]
__device__ __align__(16) __half g_wdtt [D_INNER * DT_RANK];      // [1536][96]
__device__ __align__(16) __half g_woutt[D_MODEL * D_INNER];      // [768][1536]

#define WIN_SZ  (2 * D_INNER * D_MODEL)
#define WXP_SZ  (XDBL_W * D_INNER)
#define WDT_SZ  (D_INNER * DT_RANK)
#define WOUT_SZ (D_MODEL * D_INNER)

__device__ __forceinline__ float siluf(float x) {
    return x / (1.f + __expf(-x));
}
__device__ __forceinline__ void cp_async16(unsigned saddr, const void* gptr) {
    asm volatile("cp.async.cg.shared.global [%0], [%1], 16;"
                 :: "r"(saddr), "l"(gptr));
}
__device__ __forceinline__ void ldsm_x4(uint32_t& r0, uint32_t& r1,
                                        uint32_t& r2, uint32_t& r3, unsigned a) {
    asm volatile("ldmatrix.sync.aligned.m8n8.x4.shared.b16 {%0,%1,%2,%3}, [%4];"
                 : "=r"(r0), "=r"(r1), "=r"(r2), "=r"(r3) : "r"(a));
}

// ---------------- combined weight transpose fp32[K][N] -> half[N][K] ----------------
__global__ __launch_bounds__(256) void cvt_w_all(
    const float* __restrict__ Win, const float* __restrict__ Wxp,
    const float* __restrict__ Wdt, const float* __restrict__ Wout)
{
    int idx = blockIdx.x * 256 + threadIdx.x;
    const float* src; __half* dst; int K0, N, off;
    if (idx < WIN_SZ) {
        src = Win; dst = g_wint; K0 = D_MODEL; N = 2 * D_INNER; off = idx;
    } else if (idx < WIN_SZ + WXP_SZ) {
        src = Wxp; dst = g_wxpt; K0 = D_INNER; N = XDBL_W; off = idx - WIN_SZ;
    } else if (idx < WIN_SZ + WXP_SZ + WDT_SZ) {
        src = Wdt; dst = g_wdtt; K0 = DT_RANK; N = D_INNER; off = idx - WIN_SZ - WXP_SZ;
    } else if (idx < WIN_SZ + WXP_SZ + WDT_SZ + WOUT_SZ) {
        src = Wout; dst = g_woutt; K0 = D_INNER; N = D_MODEL;
        off = idx - WIN_SZ - WXP_SZ - WDT_SZ;
    } else return;
    int k = off % K0, n = off / K0;
    dst[off] = __float2half_rn(src[(size_t)k * N + n]);
}

// ---------------- LayerNorm -> half ----------------
__global__ __launch_bounds__(256) void ln_kernel(
    const float* __restrict__ x, const float* __restrict__ g,
    const float* __restrict__ b)
{
    int row = blockIdx.x;
    int tid = threadIdx.x;
    const float* xr = x + (size_t)row * D_MODEL;
    float v0 = xr[tid], v1 = xr[tid + 256], v2 = xr[tid + 512];
    float s  = v0 + v1 + v2;
    float sq = v0 * v0 + v1 * v1 + v2 * v2;
    #pragma unroll
    for (int o = 16; o > 0; o >>= 1) {
        s  += __shfl_xor_sync(0xffffffffu, s,  o);
        sq += __shfl_xor_sync(0xffffffffu, sq, o);
    }
    __shared__ float ss[8], ssq[8];
    __shared__ float s_mu, s_rstd;
    if ((tid & 31) == 0) { ss[tid >> 5] = s; ssq[tid >> 5] = sq; }
    __syncthreads();
    if (tid == 0) {
        float ts = 0.f, tq = 0.f;
        #pragma unroll
        for (int i = 0; i < 8; i++) { ts += ss[i]; tq += ssq[i]; }
        float mu  = ts / D_MODEL;
        float var = tq / D_MODEL - mu * mu;
        s_mu = mu; s_rstd = rsqrtf(var + 1e-5f);
    }
    __syncthreads();
    float mu = s_mu, rstd = s_rstd;
    size_t base = (size_t)row * D_MODEL;
    g_xnh[base + tid      ] = __float2half_rn((v0 - mu) * rstd * g[tid      ] + b[tid      ]);
    g_xnh[base + tid + 256] = __float2half_rn((v1 - mu) * rstd * g[tid + 256] + b[tid + 256]);
    g_xnh[base + tid + 512] = __float2half_rn((v2 - mu) * rstd * g[tid + 512] + b[tid + 512]);
}

// ---------------- fp16 m16n8k16 GEMM, 5-stage cp.async + ldmatrix ----------------
// C[M,N] = A[M,K] @ Bt[N,K]^T, fp16 in, fp32 accumulate.
// 256 threads = 8 warps (4 M x 2 N). BK=32.
// EPI 0: C fp32 + Ch half (xdbl)       EPI 1: split u/v half (Ch=u, Ch2=v)
// EPI 2: softplus(acc + extra[gn])     EPI 3: acc + extra[gm*ldc+gn]
template<int BM, int BN, int EPI>
__global__ __launch_bounds__(256, 2) void h_gemm(
    const __half* __restrict__ A, int lda,
    const __half* __restrict__ Bg, int ldb,
    int K, float* __restrict__ C, int ldc,
    const float* __restrict__ extra, float* __restrict__ C2,
    __half* __restrict__ Ch, __half* __restrict__ Ch2)
{
    constexpr int BK = 32;
    constexpr int STAGES = 5;
    constexpr int ASTR = BK + 8;              // 40 halfs = 80B rows
    constexpr int ATILE = BM * ASTR;          // halfs
    constexpr int BTILE = BN * ASTR;
    constexpr int STAGE_H = ATILE + BTILE;
    constexpr int WM = BM / 4, WN = BN / 2;
    constexpr int MT = WM / 16, NT = WN / 8;
    constexpr int NP = NT / 2;                // B ldmatrix pairs
    constexpr int ACH = BM * 4;
    constexpr int BCH = BN * 4;

    extern __shared__ __half sh[];
    unsigned sbase;
    {
        uint64_t tmp = __cvta_generic_to_shared(sh);
        sbase = (unsigned)tmp;
    }

    const int tid   = threadIdx.x;
    const int lane  = tid & 31;
    const int wid   = tid >> 5;
    const int warpM = wid & 3;
    const int warpN = wid >> 2;
    const int g  = lane >> 2;
    const int t4 = lane & 3;
    const int m0 = blockIdx.y * BM;
    const int n0 = blockIdx.x * BN;
    const int wm0 = warpM * WM;
    const int wn0 = warpN * WN;
    const int KT = K / BK;

    // ldmatrix lane-relative offsets (bytes, within stage)
    const int lq = lane >> 3, li = lane & 7;
    unsigned aoff[MT], boff[NP];
    #pragma unroll
    for (int mt = 0; mt < MT; mt++)
        aoff[mt] = (unsigned)(((wm0 + mt * 16 + (lq & 1) * 8 + li) * ASTR
                               + (lq >> 1) * 8) * 2);
    #pragma unroll
    for (int p = 0; p < NP; p++)
        boff[p] = (unsigned)(ATILE * 2 + ((wn0 + (2 * p + (lq >> 1)) * 8 + li) * ASTR
                               + (lq & 1) * 8) * 2);

    auto fill = [&](int s) {
        if (s < KT) {
            int k0 = s * BK;
            unsigned ab = sbase + (unsigned)((s % STAGES) * STAGE_H) * 2u;
            unsigned bb = ab + (unsigned)ATILE * 2u;
            #pragma unroll
            for (int c = tid; c < ACH; c += 256) {
                int r = c >> 2, q = c & 3;
                cp_async16(ab + (unsigned)(r * ASTR + q * 8) * 2u,
                           &A[(size_t)(m0 + r) * lda + k0 + q * 8]);
            }
            #pragma unroll
            for (int c = tid; c < BCH; c += 256) {
                int r = c >> 2, q = c & 3;
                cp_async16(bb + (unsigned)(r * ASTR + q * 8) * 2u,
                           &Bg[(size_t)(n0 + r) * ldb + k0 + q * 8]);
            }
        }
        asm volatile("cp.async.commit_group;");
    };

    float acc[MT][NT][4];
    #pragma unroll
    for (int i = 0; i < MT; i++)
        #pragma unroll
        for (int j = 0; j < NT; j++)
            #pragma unroll
            for (int c = 0; c < 4; c++) acc[i][j][c] = 0.f;

    fill(0); fill(1); fill(2); fill(3);

    for (int it = 0; it < KT; it++) {
        asm volatile("cp.async.wait_group 3;");
        __syncthreads();
        fill(it + 4);   // writes stage (it+4)%5 == (it-1)%5, consumed last iter

        unsigned stage = sbase + (unsigned)((it % STAGES) * STAGE_H) * 2u;

        #pragma unroll
        for (int kk = 0; kk < BK; kk += 16) {
            uint32_t a[MT][4], b[NP][4];
            #pragma unroll
            for (int mt = 0; mt < MT; mt++)
                ldsm_x4(a[mt][0], a[mt][1], a[mt][2], a[mt][3],
                        stage + aoff[mt] + kk * 2);
            #pragma unroll
            for (int p = 0; p < NP; p++)
                ldsm_x4(b[p][0], b[p][1], b[p][2], b[p][3],
                        stage + boff[p] + kk * 2);
            #pragma unroll
            for (int mt = 0; mt < MT; mt++)
                #pragma unroll
                for (int nt = 0; nt < NT; nt++) {
                    uint32_t b0 = b[nt >> 1][(nt & 1) * 2];
                    uint32_t b1 = b[nt >> 1][(nt & 1) * 2 + 1];
                    asm volatile(
                        "mma.sync.aligned.m16n8k16.row.col.f32.f16.f16.f32 "
                        "{%0,%1,%2,%3},{%4,%5,%6,%7},{%8,%9},{%0,%1,%2,%3};\n"
                        : "+f"(acc[mt][nt][0]), "+f"(acc[mt][nt][1]),
                          "+f"(acc[mt][nt][2]), "+f"(acc[mt][nt][3])
                        : "r"(a[mt][0]), "r"(a[mt][1]),
                          "r"(a[mt][2]), "r"(a[mt][3]),
                          "r"(b0), "r"(b1));
                }
        }
    }

    // ---------------- epilogue ----------------
    #pragma unroll
    for (int mt = 0; mt < MT; mt++) {
        #pragma unroll
        for (int nt = 0; nt < NT; nt++) {
            int gm = m0 + wm0 + mt * 16 + g;
            int gn = n0 + wn0 + nt * 8 + 2 * t4;
            #pragma unroll
            for (int half_ = 0; half_ < 2; half_++) {
                int row = gm + half_ * 8;
                float v0 = acc[mt][nt][half_ * 2];
                float v1 = acc[mt][nt][half_ * 2 + 1];
                if (EPI == 0) {
                    *(float2*)&C[(size_t)row * ldc + gn] = make_float2(v0, v1);
                    __half2 hv;
                    hv.x = __float2half_rn(v0);
                    hv.y = __float2half_rn(v1);
                    *(__half2*)&Ch[(size_t)row * ldc + gn] = hv;
                } else if (EPI == 1) {
                    __half2 hv;
                    hv.x = __float2half_rn(v0);
                    hv.y = __float2half_rn(v1);
                    if (gn < D_INNER)
                        *(__half2*)&Ch [(size_t)row * D_INNER + gn] = hv;
                    else
                        *(__half2*)&Ch2[(size_t)row * D_INNER + gn - D_INNER] = hv;
                } else if (EPI == 2) {
                    float t0 = v0 + extra[gn];
                    float t1 = v1 + extra[gn + 1];
                    t0 = (t0 > 20.f) ? t0 : log1pf(__expf(t0));
                    t1 = (t1 > 20.f) ? t1 : log1pf(__expf(t1));
                    *(float2*)&C[(size_t)row * ldc + gn] = make_float2(t0, t1);
                } else {
                    float2 r = *(const float2*)&extra[(size_t)row * ldc + gn];
                    *(float2*)&C[(size_t)row * ldc + gn] =
                        make_float2(v0 + r.x, v1 + r.y);
                }
            }
        }
    }
}

// ---------------- causal depthwise conv (k=4) + bias + silu -> half ----------------
__global__ __launch_bounds__(256) void conv_silu_kernel(
    const float* __restrict__ cw, const float* __restrict__ cb)
{
    int idx = blockIdx.x * 256 + threadIdx.x;
    if (idx >= MTOT * (D_INNER / 4)) return;
    int d4 = idx % (D_INNER / 4);
    int m  = idx / (D_INNER / 4);
    int d  = d4 * 4;
    int l  = m & (SEQ - 1);

    float4 w0 = *(const float4*)&cw[(d    ) * 4];
    float4 w1 = *(const float4*)&cw[(d + 1) * 4];
    float4 w2 = *(const float4*)&cw[(d + 2) * 4];
    float4 w3 = *(const float4*)&cw[(d + 3) * 4];
    float wt[4][4] = {{w0.x,w0.y,w0.z,w0.w},{w1.x,w1.y,w1.z,w1.w},
                      {w2.x,w2.y,w2.z,w2.w},{w3.x,w3.y,w3.z,w3.w}};

    float4 a = *(const float4*)&cb[d];
    #pragma unroll
    for (int j = 0; j < 4; j++) {
        int li = l + j - 3;
        if (li >= 0) {
            uint2 raw = *(const uint2*)&g_uh[(size_t)(m + j - 3) * D_INNER + d];
            __half2 u01 = *(__half2*)&raw.x;
            __half2 u23 = *(__half2*)&raw.y;
            a.x = fmaf(wt[0][j], __half2float(u01.x), a.x);
            a.y = fmaf(wt[1][j], __half2float(u01.y), a.y);
            a.z = fmaf(wt[2][j], __half2float(u23.x), a.z);
            a.w = fmaf(wt[3][j], __half2float(u23.y), a.w);
        }
    }
    __half h4[4];
    h4[0] = __float2half_rn(siluf(a.x));
    h4[1] = __float2half_rn(siluf(a.y));
    h4[2] = __float2half_rn(siluf(a.z));
    h4[3] = __float2half_rn(siluf(a.w));
    *(uint2*)&g_uch[(size_t)m * D_INNER + d] = *(uint2*)h4;
}

// ---------------- selective scan (fused + gate) -> half y ----------------
__global__ __launch_bounds__(128) void scan_kernel(
    const float* __restrict__ logA, const float* __restrict__ Dp)
{
    int tid = threadIdx.x;
    int n  = tid & 15;
    int dl = tid >> 4;
    int d  = blockIdx.x * 8 + dl;
    int b  = blockIdx.y;

    float Adn = -expf(logA[d * D_STATE + n]);
    float Dd  = Dp[d];
    float h   = 0.f;

    size_t mi = (size_t)(b * SEQ) * D_INNER + d;
    size_t xi = (size_t)(b * SEQ) * XDBL_W + DT_RANK + n;

    float dlt = g_delta[mi];
    float uu  = __half2float(g_uch[mi]);
    float Bn  = g_xdbl[xi];
    float Cn  = g_xdbl[xi + D_STATE];
    float vv  = __half2float(g_vh[mi]);

    for (int l = 0; l < SEQ; l++) {
        float ndlt = 0.f, nuu = 0.f, nBn = 0.f, nCn = 0.f, nvv = 0.f;
        if (l + 1 < SEQ) {
            size_t mi2 = mi + D_INNER, xi2 = xi + XDBL_W;
            ndlt = g_delta[mi2];
            nuu  = __half2float(g_uch[mi2]);
            nBn  = g_xdbl[xi2];
            nCn  = g_xdbl[xi2 + D_STATE];
            nvv  = __half2float(g_vh[mi2]);
        }
        float e = __expf(dlt * Adn);
        h = fmaf(e, h, dlt * Bn * uu);
        float p = h * Cn;
        p += __shfl_xor_sync(0xffffffffu, p, 8, 16);
        p += __shfl_xor_sync(0xffffffffu, p, 4, 16);
        p += __shfl_xor_sync(0xffffffffu, p, 2, 16);
        p += __shfl_xor_sync(0xffffffffu, p, 1, 16);
        if (n == 0) {
            float y = (p + uu * Dd) * siluf(vv);
            g_yh[mi] = __float2half_rn(y);
        }
        mi += D_INNER; xi += XDBL_W;
        dlt = ndlt; uu = nuu; Bn = nBn; Cn = nCn; vv = nvv;
    }
}

// ---------------- launch ----------------
extern "C" void kernel_launch(void* const* d_in, const int* in_sizes, int n_in,
                              void* d_out, int out_size)
{
    const float* x      = (const float*)d_in[0];
    const float* ln_g   = (const float*)d_in[1];
    const float* ln_b   = (const float*)d_in[2];
    const float* W_in   = (const float*)d_in[3];
    const float* conv_w = (const float*)d_in[4];
    const float* conv_b = (const float*)d_in[5];
    const float* W_xprj = (const float*)d_in[6];
    const float* W_dt   = (const float*)d_in[7];
    const float* b_dt   = (const float*)d_in[8];
    const float* log_A  = (const float*)d_in[9];
    const float* D_par  = (const float*)d_in[10];
    const float* W_out  = (const float*)d_in[11];
    float* out = (float*)d_out;

    float *p_xdbl, *p_delta;
    cudaGetSymbolAddress((void**)&p_xdbl,  g_xdbl);
    cudaGetSymbolAddress((void**)&p_delta, g_delta);

    __half *p_xnh, *p_uh, *p_vh, *p_uch, *p_xdh, *p_yh;
    __half *p_wint, *p_wxpt, *p_wdtt, *p_woutt;
    cudaGetSymbolAddress((void**)&p_xnh,   g_xnh);
    cudaGetSymbolAddress((void**)&p_uh,    g_uh);
    cudaGetSymbolAddress((void**)&p_vh,    g_vh);
    cudaGetSymbolAddress((void**)&p_uch,   g_uch);
    cudaGetSymbolAddress((void**)&p_xdh,   g_xdh);
    cudaGetSymbolAddress((void**)&p_yh,    g_yh);
    cudaGetSymbolAddress((void**)&p_wint,  g_wint);
    cudaGetSymbolAddress((void**)&p_wxpt,  g_wxpt);
    cudaGetSymbolAddress((void**)&p_wdtt,  g_wdtt);
    cudaGetSymbolAddress((void**)&p_woutt, g_woutt);

    // dynamic smem: STAGES(5) * (BM+BN) * 40 halfs * 2B
    const int sm_128_128 = 5 * (128 + 128) * 40 * 2;   // 102400
    const int sm_64_32   = 5 * (64 + 32) * 40 * 2;     // 38400

    cudaFuncSetAttribute((const void*)h_gemm<128, 128, 1>,
        cudaFuncAttributeMaxDynamicSharedMemorySize, sm_128_128);
    cudaFuncSetAttribute((const void*)h_gemm<128, 128, 2>,
        cudaFuncAttributeMaxDynamicSharedMemorySize, sm_128_128);
    cudaFuncSetAttribute((const void*)h_gemm<128, 128, 3>,
        cudaFuncAttributeMaxDynamicSharedMemorySize, sm_128_128);
    cudaFuncSetAttribute((const void*)h_gemm<64, 32, 0>,
        cudaFuncAttributeMaxDynamicSharedMemorySize, sm_64_32);

    // 0. weight transpose to half (single kernel)
    {
        const int TOT = WIN_SZ + WXP_SZ + WDT_SZ + WOUT_SZ;
        cvt_w_all<<<(TOT + 255) / 256, 256>>>(W_in, W_xprj, W_dt, W_out);
    }

    // 1. LayerNorm
    ln_kernel<<<MTOT, 256>>>(x, ln_g, ln_b);

    // 2. GEMM1: uv = xn @ W_in (M=4096, N=3072, K=768), split u/v -> half
    h_gemm<128, 128, 1><<<dim3(2 * D_INNER / 128, MTOT / 128), 256, sm_128_128>>>(
        p_xnh, D_MODEL, p_wint, D_MODEL, D_MODEL,
        nullptr, D_INNER, nullptr, nullptr, p_uh, p_vh);

    // 3. depthwise causal conv + silu
    conv_silu_kernel<<<(MTOT * (D_INNER / 4) + 255) / 256, 256>>>(conv_w, conv_b);

    // 4. GEMM2: x_dbl = uc @ W_xproj (M=4096, N=128, K=1536), fp32 + half out
    h_gemm<64, 32, 0><<<dim3(XDBL_W / 32, MTOT / 64), 256, sm_64_32>>>(
        p_uch, D_INNER, p_wxpt, D_INNER, D_INNER,
        p_xdbl, XDBL_W, nullptr, nullptr, p_xdh, nullptr);

    // 5. GEMM3: delta = softplus(x_dbl[:, :96] @ W_dt + b_dt) (M=4096, N=1536, K=96)
    h_gemm<128, 128, 2><<<dim3(D_INNER / 128, MTOT / 128), 256, sm_128_128>>>(
        p_xdh, XDBL_W, p_wdtt, DT_RANK, DT_RANK,
        p_delta, D_INNER, b_dt, nullptr, nullptr, nullptr);

    // 6. fused selective scan + skip + gate
    scan_kernel<<<dim3(D_INNER / 8, BATCH), 128>>>(log_A, D_par);

    // 7. GEMM_out: out = y @ W_out + x (M=4096, N=768, K=1536)
    h_gemm<128, 128, 3><<<dim3(D_MODEL / 128, MTOT / 128), 256, sm_128_128>>>(
        p_yh, D_INNER, p_woutt, D_INNER, D_INNER,
        out, D_MODEL, x, nullptr, nullptr, nullptr);
}

// round 15
// speedup vs baseline: 2.8147x; 2.8147x over previous
#include <cuda_runtime.h>
#include <cuda_fp16.h>
#include <math.h>
#include <stdint.h>

#define D_MODEL 768
#define D_INNER 1536
#define D_STATE 16
#define DT_RANK 96
#define SEQ     2048
#define BATCH   2
#define MTOT    (BATCH * SEQ)   // 4096
#define XDBL_W  128             // DT_RANK + 2*D_STATE
#define NCH     8
#define LC      (SEQ / NCH)     // 256

// ---------------- scratch (device globals: allocation-free) ----------------
__device__ float g_xdbl [MTOT * XDBL_W];
__device__ float g_delta[MTOT * D_INNER];

__device__ __align__(16) __half g_xnh[MTOT * D_MODEL];   // LN out (GEMM1 A)
__device__ __align__(16) __half g_uh [MTOT * D_INNER];   // pre-conv u
__device__ __align__(16) __half g_vh [MTOT * D_INNER];   // gate v
__device__ __align__(16) __half g_uch[MTOT * D_INNER];   // conv+silu out
__device__ __align__(16) __half g_xdh[MTOT * XDBL_W];    // xdbl half (GEMM3 A)
__device__ __align__(16) __half g_yh [MTOT * D_INNER];   // scan out (GEMM_out A)

// chunked-scan state: index ((b*NCH+c)*D_INNER + d)*16 + n  (n contiguous)
__device__ float g_P [BATCH * NCH * D_INNER * D_STATE];
__device__ float g_q [BATCH * NCH * D_INNER * D_STATE];
__device__ float g_hs[BATCH * NCH * D_INNER * D_STATE];

// transposed half weights Wt[n][k] = W[k][n]
__device__ __align__(16) __half g_wint [2 * D_INNER * D_MODEL];
__device__ __align__(16) __half g_wxpt [XDBL_W * D_INNER];
__device__ __align__(16) __half g_wdtt [D_INNER * DT_RANK];
__device__ __align__(16) __half g_woutt[D_MODEL * D_INNER];

#define WIN_SZ  (2 * D_INNER * D_MODEL)
#define WXP_SZ  (XDBL_W * D_INNER)
#define WDT_SZ  (D_INNER * DT_RANK)
#define WOUT_SZ (D_MODEL * D_INNER)

__device__ __forceinline__ float siluf(float x) {
    return x / (1.f + __expf(-x));
}
__device__ __forceinline__ void cp_async16(unsigned saddr, const void* gptr) {
    asm volatile("cp.async.cg.shared.global [%0], [%1], 16;"
                 :: "r"(saddr), "l"(gptr));
}

// ---------------- combined weight transpose fp32[K][N] -> half[N][K] ----------------
__global__ __launch_bounds__(256) void cvt_w_all(
    const float* __restrict__ Win, const float* __restrict__ Wxp,
    const float* __restrict__ Wdt, const float* __restrict__ Wout)
{
    int idx = blockIdx.x * 256 + threadIdx.x;
    const float* src; __half* dst; int K0, N, off;
    if (idx < WIN_SZ) {
        src = Win; dst = g_wint; K0 = D_MODEL; N = 2 * D_INNER; off = idx;
    } else if (idx < WIN_SZ + WXP_SZ) {
        src = Wxp; dst = g_wxpt; K0 = D_INNER; N = XDBL_W; off = idx - WIN_SZ;
    } else if (idx < WIN_SZ + WXP_SZ + WDT_SZ) {
        src = Wdt; dst = g_wdtt; K0 = DT_RANK; N = D_INNER; off = idx - WIN_SZ - WXP_SZ;
    } else if (idx < WIN_SZ + WXP_SZ + WDT_SZ + WOUT_SZ) {
        src = Wout; dst = g_woutt; K0 = D_INNER; N = D_MODEL;
        off = idx - WIN_SZ - WXP_SZ - WDT_SZ;
    } else return;
    int k = off % K0, n = off / K0;
    dst[off] = __float2half_rn(src[(size_t)k * N + n]);
}

// ---------------- LayerNorm -> half ----------------
__global__ __launch_bounds__(256) void ln_kernel(
    const float* __restrict__ x, const float* __restrict__ g,
    const float* __restrict__ b)
{
    int row = blockIdx.x;
    int tid = threadIdx.x;
    const float* xr = x + (size_t)row * D_MODEL;
    float v0 = xr[tid], v1 = xr[tid + 256], v2 = xr[tid + 512];
    float s  = v0 + v1 + v2;
    float sq = v0 * v0 + v1 * v1 + v2 * v2;
    #pragma unroll
    for (int o = 16; o > 0; o >>= 1) {
        s  += __shfl_xor_sync(0xffffffffu, s,  o);
        sq += __shfl_xor_sync(0xffffffffu, sq, o);
    }
    __shared__ float ss[8], ssq[8];
    __shared__ float s_mu, s_rstd;
    if ((tid & 31) == 0) { ss[tid >> 5] = s; ssq[tid >> 5] = sq; }
    __syncthreads();
    if (tid == 0) {
        float ts = 0.f, tq = 0.f;
        #pragma unroll
        for (int i = 0; i < 8; i++) { ts += ss[i]; tq += ssq[i]; }
        float mu  = ts / D_MODEL;
        float var = tq / D_MODEL - mu * mu;
        s_mu = mu; s_rstd = rsqrtf(var + 1e-5f);
    }
    __syncthreads();
    float mu = s_mu, rstd = s_rstd;
    size_t base = (size_t)row * D_MODEL;
    g_xnh[base + tid      ] = __float2half_rn((v0 - mu) * rstd * g[tid      ] + b[tid      ]);
    g_xnh[base + tid + 256] = __float2half_rn((v1 - mu) * rstd * g[tid + 256] + b[tid + 256]);
    g_xnh[base + tid + 512] = __float2half_rn((v2 - mu) * rstd * g[tid + 512] + b[tid + 512]);
}

// ---------------- fp16 m16n8k16 GEMM, 4-stage cp.async (R12-proven mainloop) ----------------
// C[M,N] = A[M,K] @ Bt[N,K]^T, fp16 in, fp32 accumulate.
// 256 threads = 8 warps (4 M x 2 N). BK=32.
// EPI 0: C fp32 + Ch half (xdbl)       EPI 1: split u/v half (Ch=u, Ch2=v)
// EPI 2: softplus(acc + extra[gn])     EPI 3: acc + extra[gm*ldc+gn]
template<int BM, int BN, int EPI>
__global__ __launch_bounds__(256, 2) void h_gemm(
    const __half* __restrict__ A, int lda,
    const __half* __restrict__ Bg, int ldb,
    int K, float* __restrict__ C, int ldc,
    const float* __restrict__ extra, float* __restrict__ C2,
    __half* __restrict__ Ch, __half* __restrict__ Ch2)
{
    constexpr int BK = 32;
    constexpr int STAGES = 4;
    constexpr int ASTR = BK + 8;              // 40 halfs = 80B rows
    constexpr int ATILE = BM * ASTR;
    constexpr int BTILE = BN * ASTR;
    constexpr int STAGE_H = ATILE + BTILE;
    constexpr int WM = BM / 4, WN = BN / 2;
    constexpr int MT = WM / 16, NT = WN / 8;
    constexpr int ACH = BM * 4;
    constexpr int BCH = BN * 4;

    extern __shared__ __half sh[];
    unsigned sbase;
    {
        uint64_t tmp = __cvta_generic_to_shared(sh);
        sbase = (unsigned)tmp;
    }

    const int tid   = threadIdx.x;
    const int lane  = tid & 31;
    const int wid   = tid >> 5;
    const int warpM = wid & 3;
    const int warpN = wid >> 2;
    const int g  = lane >> 2;
    const int t4 = lane & 3;
    const int m0 = blockIdx.y * BM;
    const int n0 = blockIdx.x * BN;
    const int wm0 = warpM * WM;
    const int wn0 = warpN * WN;
    const int KT = K / BK;

    auto fill = [&](int s) {
        if (s < KT) {
            int k0 = s * BK;
            unsigned ab = sbase + (unsigned)((s % STAGES) * STAGE_H) * 2u;
            unsigned bb = ab + (unsigned)ATILE * 2u;
            #pragma unroll
            for (int c = tid; c < ACH; c += 256) {
                int r = c >> 2, q = c & 3;
                cp_async16(ab + (unsigned)(r * ASTR + q * 8) * 2u,
                           &A[(size_t)(m0 + r) * lda + k0 + q * 8]);
            }
            #pragma unroll
            for (int c = tid; c < BCH; c += 256) {
                int r = c >> 2, q = c & 3;
                cp_async16(bb + (unsigned)(r * ASTR + q * 8) * 2u,
                           &Bg[(size_t)(n0 + r) * ldb + k0 + q * 8]);
            }
        }
        asm volatile("cp.async.commit_group;");
    };

    float acc[MT][NT][4];
    #pragma unroll
    for (int i = 0; i < MT; i++)
        #pragma unroll
        for (int j = 0; j < NT; j++)
            #pragma unroll
            for (int c = 0; c < 4; c++) acc[i][j][c] = 0.f;

    fill(0); fill(1); fill(2);

    for (int it = 0; it < KT; it++) {
        asm volatile("cp.async.wait_group 2;");
        __syncthreads();
        fill(it + 3);

        const __half* As = sh + (it % STAGES) * STAGE_H;
        const __half* Bs = As + ATILE;

        #pragma unroll
        for (int kk = 0; kk < BK; kk += 16) {
            uint32_t a[MT][4], b[NT][2];
            #pragma unroll
            for (int mt = 0; mt < MT; mt++) {
                const __half* ap = As + (wm0 + mt * 16 + g) * ASTR + kk + 2 * t4;
                a[mt][0] = *(const uint32_t*)ap;
                a[mt][1] = *(const uint32_t*)(ap + 8 * ASTR);
                a[mt][2] = *(const uint32_t*)(ap + 8);
                a[mt][3] = *(const uint32_t*)(ap + 8 * ASTR + 8);
            }
            #pragma unroll
            for (int nt = 0; nt < NT; nt++) {
                const __half* bp = Bs + (wn0 + nt * 8 + g) * ASTR + kk + 2 * t4;
                b[nt][0] = *(const uint32_t*)bp;
                b[nt][1] = *(const uint32_t*)(bp + 8);
            }
            #pragma unroll
            for (int mt = 0; mt < MT; mt++)
                #pragma unroll
                for (int nt = 0; nt < NT; nt++) {
                    asm volatile(
                        "mma.sync.aligned.m16n8k16.row.col.f32.f16.f16.f32 "
                        "{%0,%1,%2,%3},{%4,%5,%6,%7},{%8,%9},{%0,%1,%2,%3};\n"
                        : "+f"(acc[mt][nt][0]), "+f"(acc[mt][nt][1]),
                          "+f"(acc[mt][nt][2]), "+f"(acc[mt][nt][3])
                        : "r"(a[mt][0]), "r"(a[mt][1]),
                          "r"(a[mt][2]), "r"(a[mt][3]),
                          "r"(b[nt][0]), "r"(b[nt][1]));
                }
        }
    }

    // ---------------- epilogue ----------------
    #pragma unroll
    for (int mt = 0; mt < MT; mt++) {
        #pragma unroll
        for (int nt = 0; nt < NT; nt++) {
            int gm = m0 + wm0 + mt * 16 + g;
            int gn = n0 + wn0 + nt * 8 + 2 * t4;
            #pragma unroll
            for (int half_ = 0; half_ < 2; half_++) {
                int row = gm + half_ * 8;
                float v0 = acc[mt][nt][half_ * 2];
                float v1 = acc[mt][nt][half_ * 2 + 1];
                if (EPI == 0) {
                    *(float2*)&C[(size_t)row * ldc + gn] = make_float2(v0, v1);
                    __half2 hv;
                    hv.x = __float2half_rn(v0);
                    hv.y = __float2half_rn(v1);
                    *(__half2*)&Ch[(size_t)row * ldc + gn] = hv;
                } else if (EPI == 1) {
                    __half2 hv;
                    hv.x = __float2half_rn(v0);
                    hv.y = __float2half_rn(v1);
                    if (gn < D_INNER)
                        *(__half2*)&Ch [(size_t)row * D_INNER + gn] = hv;
                    else
                        *(__half2*)&Ch2[(size_t)row * D_INNER + gn - D_INNER] = hv;
                } else if (EPI == 2) {
                    float t0 = v0 + extra[gn];
                    float t1 = v1 + extra[gn + 1];
                    t0 = (t0 > 20.f) ? t0 : log1pf(__expf(t0));
                    t1 = (t1 > 20.f) ? t1 : log1pf(__expf(t1));
                    *(float2*)&C[(size_t)row * ldc + gn] = make_float2(t0, t1);
                } else {
                    float2 r = *(const float2*)&extra[(size_t)row * ldc + gn];
                    *(float2*)&C[(size_t)row * ldc + gn] =
                        make_float2(v0 + r.x, v1 + r.y);
                }
            }
        }
    }
}

// ---------------- causal depthwise conv (k=4) + bias + silu -> half ----------------
__global__ __launch_bounds__(256) void conv_silu_kernel(
    const float* __restrict__ cw, const float* __restrict__ cb)
{
    int idx = blockIdx.x * 256 + threadIdx.x;
    if (idx >= MTOT * (D_INNER / 4)) return;
    int d4 = idx % (D_INNER / 4);
    int m  = idx / (D_INNER / 4);
    int d  = d4 * 4;
    int l  = m & (SEQ - 1);

    float4 w0 = *(const float4*)&cw[(d    ) * 4];
    float4 w1 = *(const float4*)&cw[(d + 1) * 4];
    float4 w2 = *(const float4*)&cw[(d + 2) * 4];
    float4 w3 = *(const float4*)&cw[(d + 3) * 4];
    float wt[4][4] = {{w0.x,w0.y,w0.z,w0.w},{w1.x,w1.y,w1.z,w1.w},
                      {w2.x,w2.y,w2.z,w2.w},{w3.x,w3.y,w3.z,w3.w}};

    float4 a = *(const float4*)&cb[d];
    #pragma unroll
    for (int j = 0; j < 4; j++) {
        int li = l + j - 3;
        if (li >= 0) {
            uint2 raw = *(const uint2*)&g_uh[(size_t)(m + j - 3) * D_INNER + d];
            __half2 u01 = *(__half2*)&raw.x;
            __half2 u23 = *(__half2*)&raw.y;
            a.x = fmaf(wt[0][j], __half2float(u01.x), a.x);
            a.y = fmaf(wt[1][j], __half2float(u01.y), a.y);
            a.z = fmaf(wt[2][j], __half2float(u23.x), a.z);
            a.w = fmaf(wt[3][j], __half2float(u23.y), a.w);
        }
    }
    __half h4[4];
    h4[0] = __float2half_rn(siluf(a.x));
    h4[1] = __float2half_rn(siluf(a.y));
    h4[2] = __float2half_rn(siluf(a.z));
    h4[3] = __float2half_rn(siluf(a.w));
    *(uint2*)&g_uch[(size_t)m * D_INNER + d] = *(uint2*)h4;
}

// ---------------- chunked selective scan ----------------
// S1: per-chunk transition P = prod(A_bar), q = local scan end (h0 = 0)
__global__ __launch_bounds__(128) void scan1_kernel(const float* __restrict__ logA)
{
    int tid = threadIdx.x;
    int n  = tid & 15;
    int d  = blockIdx.x * 8 + (tid >> 4);
    int c  = blockIdx.y;
    int b  = blockIdx.z;

    float Adn = -expf(logA[d * D_STATE + n]);
    float P = 1.f, h = 0.f;
    size_t mi = (size_t)(b * SEQ + c * LC) * D_INNER + d;
    size_t xi = (size_t)(b * SEQ + c * LC) * XDBL_W + DT_RANK + n;

    for (int l = 0; l < LC; l++) {
        float dlt = g_delta[mi];
        float uu  = __half2float(g_uch[mi]);
        float Bn  = g_xdbl[xi];
        float e = __expf(dlt * Adn);
        h = fmaf(e, h, dlt * Bn * uu);
        P *= e;
        mi += D_INNER; xi += XDBL_W;
    }
    size_t oi = ((size_t)(b * NCH + c) * D_INNER + d) * D_STATE + n;
    g_P[oi] = P;
    g_q[oi] = h;
}

// S2: serial combine across chunks -> h_start per chunk
__global__ __launch_bounds__(128) void scan2_kernel()
{
    int tid = threadIdx.x;
    int n  = tid & 15;
    int d  = blockIdx.x * 8 + (tid >> 4);
    int b  = blockIdx.y;

    float h = 0.f;
    #pragma unroll
    for (int c = 0; c < NCH; c++) {
        size_t oi = ((size_t)(b * NCH + c) * D_INNER + d) * D_STATE + n;
        g_hs[oi] = h;
        h = fmaf(g_P[oi], h, g_q[oi]);
    }
}

// S3: re-run chunk from corrected h_start, full y + gate output
__global__ __launch_bounds__(128) void scan3_kernel(
    const float* __restrict__ logA, const float* __restrict__ Dp)
{
    int tid = threadIdx.x;
    int n  = tid & 15;
    int d  = blockIdx.x * 8 + (tid >> 4);
    int c  = blockIdx.y;
    int b  = blockIdx.z;

    float Adn = -expf(logA[d * D_STATE + n]);
    float Dd  = Dp[d];
    float h   = g_hs[((size_t)(b * NCH + c) * D_INNER + d) * D_STATE + n];

    size_t mi = (size_t)(b * SEQ + c * LC) * D_INNER + d;
    size_t xi = (size_t)(b * SEQ + c * LC) * XDBL_W + DT_RANK + n;

    float dlt = g_delta[mi];
    float uu  = __half2float(g_uch[mi]);
    float Bn  = g_xdbl[xi];
    float Cn  = g_xdbl[xi + D_STATE];
    float vv  = __half2float(g_vh[mi]);

    for (int l = 0; l < LC; l++) {
        float ndlt = 0.f, nuu = 0.f, nBn = 0.f, nCn = 0.f, nvv = 0.f;
        if (l + 1 < LC) {
            size_t mi2 = mi + D_INNER, xi2 = xi + XDBL_W;
            ndlt = g_delta[mi2];
            nuu  = __half2float(g_uch[mi2]);
            nBn  = g_xdbl[xi2];
            nCn  = g_xdbl[xi2 + D_STATE];
            nvv  = __half2float(g_vh[mi2]);
        }
        float e = __expf(dlt * Adn);
        h = fmaf(e, h, dlt * Bn * uu);
        float p = h * Cn;
        p += __shfl_xor_sync(0xffffffffu, p, 8, 16);
        p += __shfl_xor_sync(0xffffffffu, p, 4, 16);
        p += __shfl_xor_sync(0xffffffffu, p, 2, 16);
        p += __shfl_xor_sync(0xffffffffu, p, 1, 16);
        if (n == 0) {
            float y = (p + uu * Dd) * siluf(vv);
            g_yh[mi] = __float2half_rn(y);
        }
        mi += D_INNER; xi += XDBL_W;
        dlt = ndlt; uu = nuu; Bn = nBn; Cn = nCn; vv = nvv;
    }
}

// ---------------- launch ----------------
extern "C" void kernel_launch(void* const* d_in, const int* in_sizes, int n_in,
                              void* d_out, int out_size)
{
    const float* x      = (const float*)d_in[0];
    const float* ln_g   = (const float*)d_in[1];
    const float* ln_b   = (const float*)d_in[2];
    const float* W_in   = (const float*)d_in[3];
    const float* conv_w = (const float*)d_in[4];
    const float* conv_b = (const float*)d_in[5];
    const float* W_xprj = (const float*)d_in[6];
    const float* W_dt   = (const float*)d_in[7];
    const float* b_dt   = (const float*)d_in[8];
    const float* log_A  = (const float*)d_in[9];
    const float* D_par  = (const float*)d_in[10];
    const float* W_out  = (const float*)d_in[11];
    float* out = (float*)d_out;

    float *p_xdbl, *p_delta;
    cudaGetSymbolAddress((void**)&p_xdbl,  g_xdbl);
    cudaGetSymbolAddress((void**)&p_delta, g_delta);

    __half *p_xnh, *p_uh, *p_vh, *p_uch, *p_xdh, *p_yh;
    __half *p_wint, *p_wxpt, *p_wdtt, *p_woutt;
    cudaGetSymbolAddress((void**)&p_xnh,   g_xnh);
    cudaGetSymbolAddress((void**)&p_uh,    g_uh);
    cudaGetSymbolAddress((void**)&p_vh,    g_vh);
    cudaGetSymbolAddress((void**)&p_uch,   g_uch);
    cudaGetSymbolAddress((void**)&p_xdh,   g_xdh);
    cudaGetSymbolAddress((void**)&p_yh,    g_yh);
    cudaGetSymbolAddress((void**)&p_wint,  g_wint);
    cudaGetSymbolAddress((void**)&p_wxpt,  g_wxpt);
    cudaGetSymbolAddress((void**)&p_wdtt,  g_wdtt);
    cudaGetSymbolAddress((void**)&p_woutt, g_woutt);

    // dynamic smem: STAGES(4) * (BM+BN) * 40 halfs * 2B
    const int sm_128_128 = 4 * (128 + 128) * 40 * 2;   // 81920
    const int sm_64_32   = 4 * (64 + 32) * 40 * 2;     // 30720

    cudaFuncSetAttribute((const void*)h_gemm<128, 128, 1>,
        cudaFuncAttributeMaxDynamicSharedMemorySize, sm_128_128);
    cudaFuncSetAttribute((const void*)h_gemm<128, 128, 2>,
        cudaFuncAttributeMaxDynamicSharedMemorySize, sm_128_128);
    cudaFuncSetAttribute((const void*)h_gemm<128, 128, 3>,
        cudaFuncAttributeMaxDynamicSharedMemorySize, sm_128_128);
    cudaFuncSetAttribute((const void*)h_gemm<64, 32, 0>,
        cudaFuncAttributeMaxDynamicSharedMemorySize, sm_64_32);

    // 0. weight transpose to half (single kernel)
    {
        const int TOT = WIN_SZ + WXP_SZ + WDT_SZ + WOUT_SZ;
        cvt_w_all<<<(TOT + 255) / 256, 256>>>(W_in, W_xprj, W_dt, W_out);
    }

    // 1. LayerNorm
    ln_kernel<<<MTOT, 256>>>(x, ln_g, ln_b);

    // 2. GEMM1: uv = xn @ W_in (M=4096, N=3072, K=768), split u/v -> half
    h_gemm<128, 128, 1><<<dim3(2 * D_INNER / 128, MTOT / 128), 256, sm_128_128>>>(
        p_xnh, D_MODEL, p_wint, D_MODEL, D_MODEL,
        nullptr, D_INNER, nullptr, nullptr, p_uh, p_vh);

    // 3. depthwise causal conv + silu
    conv_silu_kernel<<<(MTOT * (D_INNER / 4) + 255) / 256, 256>>>(conv_w, conv_b);

    // 4. GEMM2: x_dbl = uc @ W_xproj (M=4096, N=128, K=1536), fp32 + half out
    h_gemm<64, 32, 0><<<dim3(XDBL_W / 32, MTOT / 64), 256, sm_64_32>>>(
        p_uch, D_INNER, p_wxpt, D_INNER, D_INNER,
        p_xdbl, XDBL_W, nullptr, nullptr, p_xdh, nullptr);

    // 5. GEMM3: delta = softplus(x_dbl[:, :96] @ W_dt + b_dt) (M=4096, N=1536, K=96)
    h_gemm<128, 128, 2><<<dim3(D_INNER / 128, MTOT / 128), 256, sm_128_128>>>(
        p_xdh, XDBL_W, p_wdtt, DT_RANK, DT_RANK,
        p_delta, D_INNER, b_dt, nullptr, nullptr, nullptr);

    // 6. chunked selective scan: local transitions -> combine -> emit
    scan1_kernel<<<dim3(D_INNER / 8, NCH, BATCH), 128>>>(log_A);
    scan2_kernel<<<dim3(D_INNER / 8, BATCH), 128>>>();
    scan3_kernel<<<dim3(D_INNER / 8, NCH, BATCH), 128>>>(log_A, D_par);

    // 7. GEMM_out: out = y @ W_out + x (M=4096, N=768, K=1536)
    h_gemm<128, 128, 3><<<dim3(D_MODEL / 128, MTOT / 128), 256, sm_128_128>>>(
        p_yh, D_INNER, p_woutt, D_INNER, D_INNER,
        out, D_MODEL, x, nullptr, nullptr, nullptr);
}

// round 16
// speedup vs baseline: 2.9630x; 1.0527x over previous
#include <cuda_runtime.h>
#include <cuda_fp16.h>
#include <math.h>
#include <stdint.h>

#define D_MODEL 768
#define D_INNER 1536
#define D_STATE 16
#define DT_RANK 96
#define SEQ     2048
#define BATCH   2
#define MTOT    (BATCH * SEQ)   // 4096
#define XDBL_W  128             // DT_RANK + 2*D_STATE
#define NCH     32
#define LC      (SEQ / NCH)     // 64

// ---------------- scratch (device globals: allocation-free) ----------------
__device__ float g_xdbl [MTOT * XDBL_W];
__device__ float g_delta[MTOT * D_INNER];

__device__ __align__(16) __half g_xnh[MTOT * D_MODEL];   // LN out (GEMM1 A)
__device__ __align__(16) __half g_uh [MTOT * D_INNER];   // pre-conv u
__device__ __align__(16) __half g_vh [MTOT * D_INNER];   // gate v
__device__ __align__(16) __half g_uch[MTOT * D_INNER];   // conv+silu out
__device__ __align__(16) __half g_xdh[MTOT * XDBL_W];    // xdbl half (GEMM3 A)
__device__ __align__(16) __half g_yh [MTOT * D_INNER];   // scan out (GEMM_out A)

// chunked-scan state: index ((b*NCH+c)*D_INNER + d)*16 + n  (n contiguous)
__device__ float g_P [BATCH * NCH * D_INNER * D_STATE];
__device__ float g_q [BATCH * NCH * D_INNER * D_STATE];
__device__ float g_hs[BATCH * NCH * D_INNER * D_STATE];

// transposed half weights Wt[n][k] = W[k][n]
__device__ __align__(16) __half g_wint [2 * D_INNER * D_MODEL];
__device__ __align__(16) __half g_wxpt [XDBL_W * D_INNER];
__device__ __align__(16) __half g_wdtt [D_INNER * DT_RANK];
__device__ __align__(16) __half g_woutt[D_MODEL * D_INNER];

#define WIN_SZ  (2 * D_INNER * D_MODEL)
#define WXP_SZ  (XDBL_W * D_INNER)
#define WDT_SZ  (D_INNER * DT_RANK)
#define WOUT_SZ (D_MODEL * D_INNER)

__device__ __forceinline__ float siluf(float x) {
    return x / (1.f + __expf(-x));
}
__device__ __forceinline__ void cp_async16(unsigned saddr, const void* gptr) {
    asm volatile("cp.async.cg.shared.global [%0], [%1], 16;"
                 :: "r"(saddr), "l"(gptr));
}

// ---------------- combined weight transpose fp32[K][N] -> half[N][K] ----------------
__global__ __launch_bounds__(256) void cvt_w_all(
    const float* __restrict__ Win, const float* __restrict__ Wxp,
    const float* __restrict__ Wdt, const float* __restrict__ Wout)
{
    int idx = blockIdx.x * 256 + threadIdx.x;
    const float* src; __half* dst; int K0, N, off;
    if (idx < WIN_SZ) {
        src = Win; dst = g_wint; K0 = D_MODEL; N = 2 * D_INNER; off = idx;
    } else if (idx < WIN_SZ + WXP_SZ) {
        src = Wxp; dst = g_wxpt; K0 = D_INNER; N = XDBL_W; off = idx - WIN_SZ;
    } else if (idx < WIN_SZ + WXP_SZ + WDT_SZ) {
        src = Wdt; dst = g_wdtt; K0 = DT_RANK; N = D_INNER; off = idx - WIN_SZ - WXP_SZ;
    } else if (idx < WIN_SZ + WXP_SZ + WDT_SZ + WOUT_SZ) {
        src = Wout; dst = g_woutt; K0 = D_INNER; N = D_MODEL;
        off = idx - WIN_SZ - WXP_SZ - WDT_SZ;
    } else return;
    int k = off % K0, n = off / K0;
    dst[off] = __float2half_rn(src[(size_t)k * N + n]);
}

// ---------------- LayerNorm -> half ----------------
__global__ __launch_bounds__(256) void ln_kernel(
    const float* __restrict__ x, const float* __restrict__ g,
    const float* __restrict__ b)
{
    int row = blockIdx.x;
    int tid = threadIdx.x;
    const float* xr = x + (size_t)row * D_MODEL;
    float v0 = xr[tid], v1 = xr[tid + 256], v2 = xr[tid + 512];
    float s  = v0 + v1 + v2;
    float sq = v0 * v0 + v1 * v1 + v2 * v2;
    #pragma unroll
    for (int o = 16; o > 0; o >>= 1) {
        s  += __shfl_xor_sync(0xffffffffu, s,  o);
        sq += __shfl_xor_sync(0xffffffffu, sq, o);
    }
    __shared__ float ss[8], ssq[8];
    __shared__ float s_mu, s_rstd;
    if ((tid & 31) == 0) { ss[tid >> 5] = s; ssq[tid >> 5] = sq; }
    __syncthreads();
    if (tid == 0) {
        float ts = 0.f, tq = 0.f;
        #pragma unroll
        for (int i = 0; i < 8; i++) { ts += ss[i]; tq += ssq[i]; }
        float mu  = ts / D_MODEL;
        float var = tq / D_MODEL - mu * mu;
        s_mu = mu; s_rstd = rsqrtf(var + 1e-5f);
    }
    __syncthreads();
    float mu = s_mu, rstd = s_rstd;
    size_t base = (size_t)row * D_MODEL;
    g_xnh[base + tid      ] = __float2half_rn((v0 - mu) * rstd * g[tid      ] + b[tid      ]);
    g_xnh[base + tid + 256] = __float2half_rn((v1 - mu) * rstd * g[tid + 256] + b[tid + 256]);
    g_xnh[base + tid + 512] = __float2half_rn((v2 - mu) * rstd * g[tid + 512] + b[tid + 512]);
}

// ---------------- fp16 m16n8k16 GEMM, 4-stage cp.async (R12-proven mainloop) ----------------
// C[M,N] = A[M,K] @ Bt[N,K]^T, fp16 in, fp32 accumulate.
// 256 threads = 8 warps (4 M x 2 N). BK=32.
// EPI 0: C fp32 + Ch half (xdbl)       EPI 1: split u/v half (Ch=u, Ch2=v)
// EPI 2: softplus(acc + extra[gn])     EPI 3: acc + extra[gm*ldc+gn]
template<int BM, int BN, int EPI>
__global__ __launch_bounds__(256, 2) void h_gemm(
    const __half* __restrict__ A, int lda,
    const __half* __restrict__ Bg, int ldb,
    int K, float* __restrict__ C, int ldc,
    const float* __restrict__ extra, float* __restrict__ C2,
    __half* __restrict__ Ch, __half* __restrict__ Ch2)
{
    constexpr int BK = 32;
    constexpr int STAGES = 4;
    constexpr int ASTR = BK + 8;              // 40 halfs = 80B rows
    constexpr int ATILE = BM * ASTR;
    constexpr int BTILE = BN * ASTR;
    constexpr int STAGE_H = ATILE + BTILE;
    constexpr int WM = BM / 4, WN = BN / 2;
    constexpr int MT = WM / 16, NT = WN / 8;
    constexpr int ACH = BM * 4;
    constexpr int BCH = BN * 4;

    extern __shared__ __half sh[];
    unsigned sbase;
    {
        uint64_t tmp = __cvta_generic_to_shared(sh);
        sbase = (unsigned)tmp;
    }

    const int tid   = threadIdx.x;
    const int lane  = tid & 31;
    const int wid   = tid >> 5;
    const int warpM = wid & 3;
    const int warpN = wid >> 2;
    const int g  = lane >> 2;
    const int t4 = lane & 3;
    const int m0 = blockIdx.y * BM;
    const int n0 = blockIdx.x * BN;
    const int wm0 = warpM * WM;
    const int wn0 = warpN * WN;
    const int KT = K / BK;

    auto fill = [&](int s) {
        if (s < KT) {
            int k0 = s * BK;
            unsigned ab = sbase + (unsigned)((s % STAGES) * STAGE_H) * 2u;
            unsigned bb = ab + (unsigned)ATILE * 2u;
            #pragma unroll
            for (int c = tid; c < ACH; c += 256) {
                int r = c >> 2, q = c & 3;
                cp_async16(ab + (unsigned)(r * ASTR + q * 8) * 2u,
                           &A[(size_t)(m0 + r) * lda + k0 + q * 8]);
            }
            #pragma unroll
            for (int c = tid; c < BCH; c += 256) {
                int r = c >> 2, q = c & 3;
                cp_async16(bb + (unsigned)(r * ASTR + q * 8) * 2u,
                           &Bg[(size_t)(n0 + r) * ldb + k0 + q * 8]);
            }
        }
        asm volatile("cp.async.commit_group;");
    };

    float acc[MT][NT][4];
    #pragma unroll
    for (int i = 0; i < MT; i++)
        #pragma unroll
        for (int j = 0; j < NT; j++)
            #pragma unroll
            for (int c = 0; c < 4; c++) acc[i][j][c] = 0.f;

    fill(0); fill(1); fill(2);

    for (int it = 0; it < KT; it++) {
        asm volatile("cp.async.wait_group 2;");
        __syncthreads();
        fill(it + 3);

        const __half* As = sh + (it % STAGES) * STAGE_H;
        const __half* Bs = As + ATILE;

        #pragma unroll
        for (int kk = 0; kk < BK; kk += 16) {
            uint32_t a[MT][4], b[NT][2];
            #pragma unroll
            for (int mt = 0; mt < MT; mt++) {
                const __half* ap = As + (wm0 + mt * 16 + g) * ASTR + kk + 2 * t4;
                a[mt][0] = *(const uint32_t*)ap;
                a[mt][1] = *(const uint32_t*)(ap + 8 * ASTR);
                a[mt][2] = *(const uint32_t*)(ap + 8);
                a[mt][3] = *(const uint32_t*)(ap + 8 * ASTR + 8);
            }
            #pragma unroll
            for (int nt = 0; nt < NT; nt++) {
                const __half* bp = Bs + (wn0 + nt * 8 + g) * ASTR + kk + 2 * t4;
                b[nt][0] = *(const uint32_t*)bp;
                b[nt][1] = *(const uint32_t*)(bp + 8);
            }
            #pragma unroll
            for (int mt = 0; mt < MT; mt++)
                #pragma unroll
                for (int nt = 0; nt < NT; nt++) {
                    asm volatile(
                        "mma.sync.aligned.m16n8k16.row.col.f32.f16.f16.f32 "
                        "{%0,%1,%2,%3},{%4,%5,%6,%7},{%8,%9},{%0,%1,%2,%3};\n"
                        : "+f"(acc[mt][nt][0]), "+f"(acc[mt][nt][1]),
                          "+f"(acc[mt][nt][2]), "+f"(acc[mt][nt][3])
                        : "r"(a[mt][0]), "r"(a[mt][1]),
                          "r"(a[mt][2]), "r"(a[mt][3]),
                          "r"(b[nt][0]), "r"(b[nt][1]));
                }
        }
    }

    // ---------------- epilogue ----------------
    #pragma unroll
    for (int mt = 0; mt < MT; mt++) {
        #pragma unroll
        for (int nt = 0; nt < NT; nt++) {
            int gm = m0 + wm0 + mt * 16 + g;
            int gn = n0 + wn0 + nt * 8 + 2 * t4;
            #pragma unroll
            for (int half_ = 0; half_ < 2; half_++) {
                int row = gm + half_ * 8;
                float v0 = acc[mt][nt][half_ * 2];
                float v1 = acc[mt][nt][half_ * 2 + 1];
                if (EPI == 0) {
                    *(float2*)&C[(size_t)row * ldc + gn] = make_float2(v0, v1);
                    __half2 hv;
                    hv.x = __float2half_rn(v0);
                    hv.y = __float2half_rn(v1);
                    *(__half2*)&Ch[(size_t)row * ldc + gn] = hv;
                } else if (EPI == 1) {
                    __half2 hv;
                    hv.x = __float2half_rn(v0);
                    hv.y = __float2half_rn(v1);
                    if (gn < D_INNER)
                        *(__half2*)&Ch [(size_t)row * D_INNER + gn] = hv;
                    else
                        *(__half2*)&Ch2[(size_t)row * D_INNER + gn - D_INNER] = hv;
                } else if (EPI == 2) {
                    float t0 = v0 + extra[gn];
                    float t1 = v1 + extra[gn + 1];
                    t0 = (t0 > 20.f) ? t0 : log1pf(__expf(t0));
                    t1 = (t1 > 20.f) ? t1 : log1pf(__expf(t1));
                    *(float2*)&C[(size_t)row * ldc + gn] = make_float2(t0, t1);
                } else {
                    float2 r = *(const float2*)&extra[(size_t)row * ldc + gn];
                    *(float2*)&C[(size_t)row * ldc + gn] =
                        make_float2(v0 + r.x, v1 + r.y);
                }
            }
        }
    }
}

// ---------------- causal depthwise conv (k=4) + bias + silu, 2 tokens/thread ----------------
__global__ __launch_bounds__(256) void conv_silu_kernel(
    const float* __restrict__ cw, const float* __restrict__ cb)
{
    int idx = blockIdx.x * 256 + threadIdx.x;    // over (MTOT/2) * (D_INNER/4)
    if (idx >= (MTOT / 2) * (D_INNER / 4)) return;
    int d4 = idx % (D_INNER / 4);
    int t  = idx / (D_INNER / 4);
    int m  = t * 2;                 // first of the token pair (same batch: SEQ even)
    int d  = d4 * 4;
    int l  = m & (SEQ - 1);

    float4 w0 = *(const float4*)&cw[(d    ) * 4];
    float4 w1 = *(const float4*)&cw[(d + 1) * 4];
    float4 w2 = *(const float4*)&cw[(d + 2) * 4];
    float4 w3 = *(const float4*)&cw[(d + 3) * 4];
    float wt[4][4] = {{w0.x,w0.y,w0.z,w0.w},{w1.x,w1.y,w1.z,w1.w},
                      {w2.x,w2.y,w2.z,w2.w},{w3.x,w3.y,w3.z,w3.w}};

    // rows[r] = u at sequence offset l + r - 3 (r = 0..4); zero if out of range
    float rows[5][4];
    #pragma unroll
    for (int r = 0; r < 5; r++) {
        if (l + r - 3 >= 0) {
            uint2 raw = *(const uint2*)&g_uh[(size_t)(m + r - 3) * D_INNER + d];
            __half2 u01 = *(__half2*)&raw.x;
            __half2 u23 = *(__half2*)&raw.y;
            rows[r][0] = __half2float(u01.x);
            rows[r][1] = __half2float(u01.y);
            rows[r][2] = __half2float(u23.x);
            rows[r][3] = __half2float(u23.y);
        } else {
            rows[r][0] = rows[r][1] = rows[r][2] = rows[r][3] = 0.f;
        }
    }

    float4 bias = *(const float4*)&cb[d];
    float bb[4] = {bias.x, bias.y, bias.z, bias.w};

    #pragma unroll
    for (int o = 0; o < 2; o++) {
        __half h4[4];
        #pragma unroll
        for (int i = 0; i < 4; i++) {
            float a = bb[i];
            #pragma unroll
            for (int j = 0; j < 4; j++)
                a = fmaf(wt[i][j], rows[j + o][i], a);
            h4[i] = __float2half_rn(siluf(a));
        }
        *(uint2*)&g_uch[(size_t)(m + o) * D_INNER + d] = *(uint2*)h4;
    }
}

// ---------------- chunked selective scan ----------------
// S1: per-chunk transition P = prod(A_bar), q = local scan end (h0 = 0)
__global__ __launch_bounds__(128) void scan1_kernel(const float* __restrict__ logA)
{
    int tid = threadIdx.x;
    int n  = tid & 15;
    int d  = blockIdx.x * 8 + (tid >> 4);
    int c  = blockIdx.y;
    int b  = blockIdx.z;

    float Adn = -expf(logA[d * D_STATE + n]);
    float P = 1.f, h = 0.f;
    size_t mi = (size_t)(b * SEQ + c * LC) * D_INNER + d;
    size_t xi = (size_t)(b * SEQ + c * LC) * XDBL_W + DT_RANK + n;

    for (int l = 0; l < LC; l++) {
        float dlt = g_delta[mi];
        float uu  = __half2float(g_uch[mi]);
        float Bn  = g_xdbl[xi];
        float e = __expf(dlt * Adn);
        h = fmaf(e, h, dlt * Bn * uu);
        P *= e;
        mi += D_INNER; xi += XDBL_W;
    }
    size_t oi = ((size_t)(b * NCH + c) * D_INNER + d) * D_STATE + n;
    g_P[oi] = P;
    g_q[oi] = h;
}

// S2: serial combine across chunks -> h_start per chunk
__global__ __launch_bounds__(128) void scan2_kernel()
{
    int tid = threadIdx.x;
    int n  = tid & 15;
    int d  = blockIdx.x * 8 + (tid >> 4);
    int b  = blockIdx.y;

    float h = 0.f;
    #pragma unroll
    for (int c = 0; c < NCH; c++) {
        size_t oi = ((size_t)(b * NCH + c) * D_INNER + d) * D_STATE + n;
        g_hs[oi] = h;
        h = fmaf(g_P[oi], h, g_q[oi]);
    }
}

// S3: re-run chunk from corrected h_start, full y + gate output
__global__ __launch_bounds__(128) void scan3_kernel(
    const float* __restrict__ logA, const float* __restrict__ Dp)
{
    int tid = threadIdx.x;
    int n  = tid & 15;
    int d  = blockIdx.x * 8 + (tid >> 4);
    int c  = blockIdx.y;
    int b  = blockIdx.z;

    float Adn = -expf(logA[d * D_STATE + n]);
    float Dd  = Dp[d];
    float h   = g_hs[((size_t)(b * NCH + c) * D_INNER + d) * D_STATE + n];

    size_t mi = (size_t)(b * SEQ + c * LC) * D_INNER + d;
    size_t xi = (size_t)(b * SEQ + c * LC) * XDBL_W + DT_RANK + n;

    float dlt = g_delta[mi];
    float uu  = __half2float(g_uch[mi]);
    float Bn  = g_xdbl[xi];
    float Cn  = g_xdbl[xi + D_STATE];
    float vv  = __half2float(g_vh[mi]);

    for (int l = 0; l < LC; l++) {
        float ndlt = 0.f, nuu = 0.f, nBn = 0.f, nCn = 0.f, nvv = 0.f;
        if (l + 1 < LC) {
            size_t mi2 = mi + D_INNER, xi2 = xi + XDBL_W;
            ndlt = g_delta[mi2];
            nuu  = __half2float(g_uch[mi2]);
            nBn  = g_xdbl[xi2];
            nCn  = g_xdbl[xi2 + D_STATE];
            nvv  = __half2float(g_vh[mi2]);
        }
        float e = __expf(dlt * Adn);
        h = fmaf(e, h, dlt * Bn * uu);
        float p = h * Cn;
        p += __shfl_xor_sync(0xffffffffu, p, 8, 16);
        p += __shfl_xor_sync(0xffffffffu, p, 4, 16);
        p += __shfl_xor_sync(0xffffffffu, p, 2, 16);
        p += __shfl_xor_sync(0xffffffffu, p, 1, 16);
        if (n == 0) {
            float y = (p + uu * Dd) * siluf(vv);
            g_yh[mi] = __float2half_rn(y);
        }
        mi += D_INNER; xi += XDBL_W;
        dlt = ndlt; uu = nuu; Bn = nBn; Cn = nCn; vv = nvv;
    }
}

// ---------------- launch ----------------
extern "C" void kernel_launch(void* const* d_in, const int* in_sizes, int n_in,
                              void* d_out, int out_size)
{
    const float* x      = (const float*)d_in[0];
    const float* ln_g   = (const float*)d_in[1];
    const float* ln_b   = (const float*)d_in[2];
    const float* W_in   = (const float*)d_in[3];
    const float* conv_w = (const float*)d_in[4];
    const float* conv_b = (const float*)d_in[5];
    const float* W_xprj = (const float*)d_in[6];
    const float* W_dt   = (const float*)d_in[7];
    const float* b_dt   = (const float*)d_in[8];
    const float* log_A  = (const float*)d_in[9];
    const float* D_par  = (const float*)d_in[10];
    const float* W_out  = (const float*)d_in[11];
    float* out = (float*)d_out;

    float *p_xdbl, *p_delta;
    cudaGetSymbolAddress((void**)&p_xdbl,  g_xdbl);
    cudaGetSymbolAddress((void**)&p_delta, g_delta);

    __half *p_xnh, *p_uh, *p_vh, *p_uch, *p_xdh, *p_yh;
    __half *p_wint, *p_wxpt, *p_wdtt, *p_woutt;
    cudaGetSymbolAddress((void**)&p_xnh,   g_xnh);
    cudaGetSymbolAddress((void**)&p_uh,    g_uh);
    cudaGetSymbolAddress((void**)&p_vh,    g_vh);
    cudaGetSymbolAddress((void**)&p_uch,   g_uch);
    cudaGetSymbolAddress((void**)&p_xdh,   g_xdh);
    cudaGetSymbolAddress((void**)&p_yh,    g_yh);
    cudaGetSymbolAddress((void**)&p_wint,  g_wint);
    cudaGetSymbolAddress((void**)&p_wxpt,  g_wxpt);
    cudaGetSymbolAddress((void**)&p_wdtt,  g_wdtt);
    cudaGetSymbolAddress((void**)&p_woutt, g_woutt);

    // dynamic smem: STAGES(4) * (BM+BN) * 40 halfs * 2B
    const int sm_128_128 = 4 * (128 + 128) * 40 * 2;   // 81920
    const int sm_128_64  = 4 * (128 + 64) * 40 * 2;    // 61440
    const int sm_64_32   = 4 * (64 + 32) * 40 * 2;     // 30720

    cudaFuncSetAttribute((const void*)h_gemm<128, 128, 1>,
        cudaFuncAttributeMaxDynamicSharedMemorySize, sm_128_128);
    cudaFuncSetAttribute((const void*)h_gemm<128, 128, 2>,
        cudaFuncAttributeMaxDynamicSharedMemorySize, sm_128_128);
    cudaFuncSetAttribute((const void*)h_gemm<128, 64, 3>,
        cudaFuncAttributeMaxDynamicSharedMemorySize, sm_128_64);
    cudaFuncSetAttribute((const void*)h_gemm<64, 32, 0>,
        cudaFuncAttributeMaxDynamicSharedMemorySize, sm_64_32);

    // 0. weight transpose to half (single kernel)
    {
        const int TOT = WIN_SZ + WXP_SZ + WDT_SZ + WOUT_SZ;
        cvt_w_all<<<(TOT + 255) / 256, 256>>>(W_in, W_xprj, W_dt, W_out);
    }

    // 1. LayerNorm
    ln_kernel<<<MTOT, 256>>>(x, ln_g, ln_b);

    // 2. GEMM1: uv = xn @ W_in (M=4096, N=3072, K=768), split u/v -> half
    h_gemm<128, 128, 1><<<dim3(2 * D_INNER / 128, MTOT / 128), 256, sm_128_128>>>(
        p_xnh, D_MODEL, p_wint, D_MODEL, D_MODEL,
        nullptr, D_INNER, nullptr, nullptr, p_uh, p_vh);

    // 3. depthwise causal conv + silu (2 tokens/thread)
    conv_silu_kernel<<<((MTOT / 2) * (D_INNER / 4) + 255) / 256, 256>>>(conv_w, conv_b);

    // 4. GEMM2: x_dbl = uc @ W_xproj (M=4096, N=128, K=1536), fp32 + half out
    h_gemm<64, 32, 0><<<dim3(XDBL_W / 32, MTOT / 64), 256, sm_64_32>>>(
        p_uch, D_INNER, p_wxpt, D_INNER, D_INNER,
        p_xdbl, XDBL_W, nullptr, nullptr, p_xdh, nullptr);

    // 5. GEMM3: delta = softplus(x_dbl[:, :96] @ W_dt + b_dt) (M=4096, N=1536, K=96)
    h_gemm<128, 128, 2><<<dim3(D_INNER / 128, MTOT / 128), 256, sm_128_128>>>(
        p_xdh, XDBL_W, p_wdtt, DT_RANK, DT_RANK,
        p_delta, D_INNER, b_dt, nullptr, nullptr, nullptr);

    // 6. chunked selective scan: local transitions -> combine -> emit
    scan1_kernel<<<dim3(D_INNER / 8, NCH, BATCH), 128>>>(log_A);
    scan2_kernel<<<dim3(D_INNER / 8, BATCH), 128>>>();
    scan3_kernel<<<dim3(D_INNER / 8, NCH, BATCH), 128>>>(log_A, D_par);

    // 7. GEMM_out: out = y @ W_out + x (M=4096, N=768, K=1536)  [128x64 tiles]
    h_gemm<128, 64, 3><<<dim3(D_MODEL / 64, MTOT / 128), 256, sm_128_64>>>(
        p_yh, D_INNER, p_woutt, D_INNER, D_INNER,
        out, D_MODEL, x, nullptr, nullptr, nullptr);
}